// round 10
// baseline (speedup 1.0000x reference)
#include <cuda_runtime.h>

// HoG layer, fully dense-traffic version.
//   input  x: (1, 3, 4096, 4096) f32 ; output feat: (511, 511, 36) f32
// Phase 1 (x2 chunks): warps stage rows {8cy+6,7,8} densely (float4, channels
//   summed, OOB zero-filled) into sbuf; one thread per cell extracts 4 values
//   via LDS and writes all 9 hist bins (no zero pass, no validity checks).
// Phase 2 (x2 chunks): register-light normalize into sbuf (reused as obuf),
//   then coalesced float4 copy to gmem.

#define IMG   4096
#define CELLS 512
#define OUTD  511
#define TC    16
#define HW    (TC + 1)      // 17
#define NT    256
#define SEGW  136           // floats per staged row
#define NSEG  34            // float4 per staged row
#define CR    8             // block-rows per phase-2 chunk
#define OBF4  (CR * TC * 9) // 1152 float4 per phase-2 chunk

__global__ __launch_bounds__(NT, 6)
void hog_fused_kernel(const float* __restrict__ x, float* __restrict__ out)
{
    // sbuf: phase 1 rowbuf (27*136 = 3672 floats) / phase 2 obuf (4608 floats)
    __shared__ __align__(16) float sbuf[CR * TC * 36];   // 18432 B
    __shared__ __align__(16) float hist[HW * HW * 9];    // 10404 B

    const int cx0 = blockIdx.x * TC;
    const int cy0 = blockIdx.y * TC;
    const int tid = threadIdx.x;
    const int wid = tid >> 5;
    const int lane = tid & 31;
    const long chs = (long)IMG * IMG;
    const int gcb = 8 * cx0 + 4;       // global col base of the staged window

    // ---- Phase 1: two chunks of cell-rows (9 + 8) ----
    #pragma unroll
    for (int chunk = 0; chunk < 2; chunk++) {
        const int r0 = (chunk == 0) ? 0 : 9;
        const int nr = (chunk == 0) ? 9 : 8;
        const int nrf = nr * 3;        // staged rows this chunk (27 / 24)

        // Stage: warp handles staged-row rf = wid + 8k (contiguous 136-float
        // rows; lane covers seg 0..31, lanes 0..1 also cover segs 32..33).
        #pragma unroll
        for (int k = 0; k < 4; k++) {
            const int rf = wid + 8 * k;
            if (rf < nrf) {
                const int lcy = rf / 3;
                const int r   = rf - 3 * lcy;
                const int grow = 8 * (cy0 + r0 + lcy) + 6 + r;
                const bool rok = (grow < IMG);
                const float* rp = x + (long)grow * IMG;
                const float4 z = make_float4(0.f, 0.f, 0.f, 0.f);

                {   // seg = lane
                    const int col = gcb + 4 * lane;
                    const bool ok = rok && (col < IMG);
                    const float4 a = ok ? *(const float4*)(rp + col)           : z;
                    const float4 b = ok ? *(const float4*)(rp + col + chs)     : z;
                    const float4 c = ok ? *(const float4*)(rp + col + 2 * chs) : z;
                    float4 s;
                    s.x = a.x + b.x + c.x;  s.y = a.y + b.y + c.y;
                    s.z = a.z + b.z + c.z;  s.w = a.w + b.w + c.w;
                    *(float4*)&sbuf[rf * SEGW + 4 * lane] = s;
                }
                if (lane < 2) {   // seg = 32 + lane
                    const int col = gcb + 4 * (32 + lane);
                    const bool ok = rok && (col < IMG);
                    const float4 a = ok ? *(const float4*)(rp + col)           : z;
                    const float4 b = ok ? *(const float4*)(rp + col + chs)     : z;
                    const float4 c = ok ? *(const float4*)(rp + col + 2 * chs) : z;
                    float4 s;
                    s.x = a.x + b.x + c.x;  s.y = a.y + b.y + c.y;
                    s.z = a.z + b.z + c.z;  s.w = a.w + b.w + c.w;
                    *(float4*)&sbuf[rf * SEGW + 4 * (32 + lane)] = s;
                }
            }
        }
        __syncthreads();

        // Bin: one cell per thread; OOB already zero-filled -> no checks.
        const int ncells = nr * HW;    // 153 / 136
        if (tid < ncells) {
            const int lcy = tid / HW;              // local to chunk
            const int lcx = tid - lcy * HW;
            const float* rb = &sbuf[(3 * lcy) * SEGW + 8 * lcx];
            const float su = rb[3];                // row 8cy+6, col px
            const float sl = rb[SEGW + 2];         // row 8cy+7, col px-1
            const float sr = rb[SEGW + 4];         // row 8cy+7, col px+1
            const float sd = rb[2 * SEGW + 3];     // row 8cy+8, col px

            const float gv = sd - su;
            const float gh = sr - sl;
            const float mag = sqrtf(gv * gv + gh * gh + 1e-6f);
            const float ang = fabsf(atanf(gh / (gv + 1e-9f)))
                              * (180.0f / 3.14159265358979323846f);

            const float t  = ang * 0.05f;          // ang / 20
            const int   ji = (int)floorf(t - 0.5f);  // in [-1, 4]
            const float vj  = mag * ((float)ji + 1.5f - t);
            const float vj1 = mag - vj;
            const int i0 = (ji < 0) ? 8 : ji;      // mod(ji, 9)
            const int i1 = ji + 1;                 // never == i0

            float* hrow = &hist[((r0 + lcy) * HW + lcx) * 9];
            #pragma unroll
            for (int b = 0; b < 9; b++)
                hrow[b] = (b == i0) ? vj : ((b == i1) ? vj1 : 0.0f);
        }
        __syncthreads();
    }

    // ---- Phase 2: two chunks of 8 block-rows; sbuf reused as obuf ----
    const int nbx = (cx0 + TC <= OUTD) ? TC : (OUTD - cx0);   // 16 or 15

    #pragma unroll
    for (int ck = 0; ck < 2; ck++) {
        const int oyb = cy0 + ck * CR;
        const int rows_c = (oyb + CR <= OUTD) ? CR : (OUTD - oyb); // 8 or 7

        // 2a: threads 0..127 normalize one block each (two-pass over hist).
        if (tid < CR * TC) {
            const int ly = ck * CR + (tid >> 4);
            const int lx = tid & 15;
            if ((oyb + (tid >> 4)) < OUTD && (cx0 + lx) < OUTD) {
                const float* hb = &hist[(ly * HW + lx) * 9];

                float ss = 0.f;
                #pragma unroll
                for (int s = 0; s < 4; s++) {
                    const float* h = hb + ((s & 1) ? 9 : 0) + ((s & 2) ? HW * 9 : 0);
                    #pragma unroll
                    for (int b = 0; b < 9; b++) ss += h[b] * h[b];
                }
                const float inv = 1.0f / (sqrtf(ss) + 1e-9f);

                float4* o4 = reinterpret_cast<float4*>(&sbuf[tid * 36]);
                #pragma unroll
                for (int g = 0; g < 9; g++) {
                    float w[4];
                    #pragma unroll
                    for (int kk = 0; kk < 4; kk++) {
                        const int i = 4 * g + kk;          // 0..35
                        const int s = i / 9;               // const after unroll
                        const int b = i - s * 9;
                        w[kk] = hb[((s & 1) ? 9 : 0) + ((s & 2) ? HW * 9 : 0) + b] * inv;
                    }
                    o4[g] = make_float4(w[0], w[1], w[2], w[3]);
                }
            }
        }
        __syncthreads();

        // 2b: coalesced copy SMEM -> GMEM
        if (rows_c == CR && nbx == TC) {
            const float4* src = reinterpret_cast<const float4*>(sbuf);
            #pragma unroll
            for (int k = 0; k < (OBF4 + NT - 1) / NT; k++) {
                const int f = tid + k * NT;
                if (f < OBF4) {
                    const int r = f / (TC * 9);
                    const int i = f - r * (TC * 9);
                    float4* dst = reinterpret_cast<float4*>(
                        out + ((size_t)(oyb + r) * OUTD + cx0) * 36);
                    dst[i] = src[r * (TC * 9) + i];
                }
            }
        } else {
            const int row_f4 = nbx * 9;
            for (int r = 0; r < rows_c; r++) {
                const float4* src = reinterpret_cast<const float4*>(&sbuf[r * TC * 36]);
                float4* dst = reinterpret_cast<float4*>(
                    out + ((size_t)(oyb + r) * OUTD + cx0) * 36);
                for (int i = tid; i < row_f4; i += NT) dst[i] = src[i];
            }
        }
        __syncthreads();   // sbuf reused by next chunk / safe at end
    }
}

extern "C" void kernel_launch(void* const* d_in, const int* in_sizes, int n_in,
                              void* d_out, int out_size)
{
    const float* x = (const float*)d_in[0];
    float* out = (float*)d_out;
    dim3 grid(CELLS / TC, CELLS / TC);   // 32 x 32 tiles = 1024 CTAs
    hog_fused_kernel<<<grid, NT>>>(x, out);
}